// round 11
// baseline (speedup 1.0000x reference)
#include <cuda_runtime.h>

// SigKerMMD with triangle symmetry (work = 2080 + 4096 + 2080 = 8256 pairs).
// out = (sum_XX - 2*sum_XY + sum_YY) / 4096
//
// R11: ILP doubling. Only ~2064 warps of work exist at 4 pairs/warp -> 3.5
// warps/SMSP -> latency exposed (issue 62%, flat across instr/path cuts).
// Fix: each 8-lane wavefront group now advances TWO independent pairs (P,Q)
// with fully separate register state -> two independent dependency chains per
// warp -> per-warp IPC ~doubles, SMSP issue port saturates. 8 pairs/warp,
// 1032 warps, 258 blocks x 128 threads (4 warps/block to cover all SMSPs).

#define SEQ 32
#define CH 5
#define SEQCH (SEQ * CH)          // 160
#define NTRI 2080                 // 64*65/2
#define NPAIRS (NTRI + 4096 + NTRI)          // 8256
#define PAIRS_PER_WARP 8
#define NWARPS (NPAIRS / PAIRS_PER_WARP)     // 1032
#define WARPS_PER_BLOCK 4
#define NBLOCKS (NWARPS / WARPS_PER_BLOCK)   // 258
#define THREADS_PER_BLOCK (WARPS_PER_BLOCK * 32)

#define AA_RP 31
#define AA_STRIDE (AA_RP * 32)    // 992 floats (3968B, float4-aligned) per pair

__device__ float g_aa[(size_t)NPAIRS * AA_STRIDE];   // ~32.8 MB staging (L2)
__device__ float g_block[NBLOCKS];
__device__ unsigned int g_done = 0;

// decode work item -> (seg, a, b, weight). Layout:
//   [0, 2080)      XX upper triangle (a<=b), weight 2 off-diag / 1 diag
//   [2080, 6176)   XY full, weight -2
//   [6176, 8256)   YY upper triangle, weight 2 off-diag / 1 diag
__device__ __forceinline__ void decode_pair(int w, int& seg, int& a, int& b, float& wgt)
{
    if (w < NTRI) {
        seg = 0;
        int t = w;
        int ar = (int)((129.0f - sqrtf(16641.0f - 8.0f * (float)t)) * 0.5f);
        if (ar < 0) ar = 0;
        while (ar > 0 && (ar * 64 - (ar * (ar - 1)) / 2) > t) ar--;
        while (((ar + 1) * 64 - ((ar + 1) * ar) / 2) <= t) ar++;
        a = ar;
        b = ar + (t - (ar * 64 - (ar * (ar - 1)) / 2));
        wgt = (a == b) ? 1.0f : 2.0f;
    } else if (w < NTRI + 4096) {
        seg = 1;
        int p = w - NTRI;
        a = p >> 6;
        b = p & 63;
        wgt = -2.0f;
    } else {
        seg = 2;
        int t = w - (NTRI + 4096);
        int ar = (int)((129.0f - sqrtf(16641.0f - 8.0f * (float)t)) * 0.5f);
        if (ar < 0) ar = 0;
        while (ar > 0 && (ar * 64 - (ar * (ar - 1)) / 2) > t) ar--;
        while (((ar + 1) * 64 - ((ar + 1) * ar) / 2) <= t) ar++;
        a = ar;
        b = ar + (t - (ar * 64 - (ar * (ar - 1)) / 2));
        wgt = (a == b) ? 1.0f : 2.0f;
    }
}

__global__ __launch_bounds__(THREADS_PER_BLOCK)
void sig_kernel(const float* __restrict__ x,
                const float* __restrict__ y,
                const float* __restrict__ sig,
                float* __restrict__ out)
{
    __shared__ float sh_xa[WARPS_PER_BLOCK][SEQCH];
    __shared__ float sh_xn[WARPS_PER_BLOCK][SEQ];
    __shared__ float sh_res[WARPS_PER_BLOCK];
    __shared__ int   sh_last;
    __shared__ float sh_red[THREADS_PER_BLOCK];

    const int warp = threadIdx.x >> 5;
    const int lane = threadIdx.x & 31;
    const int wg   = blockIdx.x * WARPS_PER_BLOCK + warp;  // warp id 0..1031

    // channel scales for mu = [x0, x1*s0, x2*s1, x3*s2, x4*s3]
    float cs[CH];
    cs[0] = 1.0f;
    cs[1] = sig[0]; cs[2] = sig[1]; cs[3] = sig[2]; cs[4] = sig[3];

    // ======== Phase A: gram + dyadic increments for 8 pairs (full warp) ========
    #pragma unroll 1
    for (int g = 0; g < PAIRS_PER_WARP; g++) {
        const int w = wg * PAIRS_PER_WARP + g;    // work item 0..8255
        int seg, a, b; float wdummy;
        decode_pair(w, seg, a, b, wdummy);

        const float* Aptr = ((seg < 2) ? x : y) + a * SEQCH;
        const bool   Ascale = (seg < 2);
        const float* Bptr = ((seg == 0) ? x : y) + b * SEQCH;
        const bool   Bscale = (seg == 0);

        // load A sequence (possibly sigma-scaled) into shared
        #pragma unroll
        for (int idx = lane; idx < SEQCH; idx += 32) {
            float v = Aptr[idx];
            if (Ascale) v *= cs[idx % CH];
            sh_xa[warp][idx] = v;
        }
        __syncwarp();

        // per-row squared norms of A
        {
            float s = 0.0f;
            #pragma unroll
            for (int c = 0; c < CH; c++) {
                float v = sh_xa[warp][lane * CH + c];
                s += v * v;
            }
            sh_xn[warp][lane] = s;
        }

        // B column (lane n) into registers
        float yb[CH];
        float yn = 0.0f;
        #pragma unroll
        for (int c = 0; c < CH; c++) {
            float v = Bptr[lane * CH + c];
            if (Bscale) v *= cs[c];
            yb[c] = v;
            yn += v * v;
        }
        __syncwarp();

        // gram column + second differences -> aa (fp32) to global staging
        float* aout = g_aa + (size_t)w * AA_STRIDE + lane;
        float gprev = 0.0f;
        #pragma unroll 4
        for (int m = 0; m < SEQ; m++) {
            float dot = 0.0f;
            #pragma unroll
            for (int c = 0; c < CH; c++)
                dot = fmaf(sh_xa[warp][m * CH + c], yb[c], dot);
            float d2 = sh_xn[warp][m] + yn - 2.0f * dot;
            float gv = __expf(-d2);         // RBF_SIGMA = 1.0
            if (m > 0) {
                float cd  = gv - gprev;
                float cdn = __shfl_down_sync(0xffffffffu, cd, 1);
                float aa = (lane < 31) ? (cdn - cd) * 0.25f : 0.0f;
                aout[(m - 1) * 32] = aa;
            }
            gprev = gv;
        }
        __syncwarp();
    }

    // make this warp's aa stores visible to its own cross-lane reads
    __threadfence_block();
    __syncwarp();

    // ======== Phase B: wavefront PDE, TWO pairs per 8-lane group ========
    // K is (63x63) per pair, K[0][*]=K[*][0]=1.
    // K[i][j] = (K[i][j-1]+K[i-1][j])*c1 - K[i-1][j-1]*c2
    //   n_j = c1_j*n_{j-1} + b_j,  b_j = c1_j*k_j - c2_j*k_{j-1}
    // thread t owns cols 8t+1..8t+8 of BOTH pairs; step s computes row s-t+1.
    // Two independent chains per thread -> ILP hides the shfl+FFMA latency.
    const int grp = lane >> 3;                   // group within warp (0..3)
    const int t   = lane & 7;                    // wavefront thread (0..7)

    float k[2][8], c1[2][4], c2[2][4], inL[2], inD[2], wgt[2];
    float4 cur[2], nxt[2], nx2[2];
    const float4* ap[2];

    #pragma unroll
    for (int p = 0; p < 2; p++) {
        const int pair = wg * PAIRS_PER_WARP + grp * 2 + p;
        int sg, pa, pb;
        decode_pair(pair, sg, pa, pb, wgt[p]);
        ap[p] = reinterpret_cast<const float4*>(
                    g_aa + (size_t)pair * AA_STRIDE) + t;
        cur[p] = ap[p][0];
        nxt[p] = ap[p][8];
        nx2[p] = ap[p][16];
        ap[p] += 24;
        #pragma unroll
        for (int j = 0; j < 8; j++) k[p][j] = 1.0f;
        #pragma unroll
        for (int j = 0; j < 4; j++) { c1[p][j] = 1.0f; c2[p][j] = 1.0f; }
        inL[p] = 1.0f;
        inD[p] = 1.0f;
    }
    int remaining = 31 - 3;

    #pragma unroll 2
    for (int s = 0; s < 69; s++) {
        unsigned r = (unsigned)(s - t);                    // i-1
        if (r < 62u) {
            if (!(r & 1u)) {                               // new row-pair coeffs
                #pragma unroll
                for (int p = 0; p < 2; p++) {
                    float q;
                    q = cur[p].x * cur[p].x * (1.0f / 12.0f);
                    c1[p][0] = 1.0f + 0.5f * cur[p].x + q;  c2[p][0] = 1.0f - q;
                    q = cur[p].y * cur[p].y * (1.0f / 12.0f);
                    c1[p][1] = 1.0f + 0.5f * cur[p].y + q;  c2[p][1] = 1.0f - q;
                    q = cur[p].z * cur[p].z * (1.0f / 12.0f);
                    c1[p][2] = 1.0f + 0.5f * cur[p].z + q;  c2[p][2] = 1.0f - q;
                    q = cur[p].w * cur[p].w * (1.0f / 12.0f);
                    c1[p][3] = 1.0f + 0.5f * cur[p].w + q;  c2[p][3] = 1.0f - q;
                    cur[p] = nxt[p]; nxt[p] = nx2[p];
                }
                if (remaining > 0) {                        // stay in-bounds
                    nx2[0] = *ap[0]; ap[0] += 8;
                    nx2[1] = *ap[1]; ap[1] += 8;
                    remaining--;
                }
            }
            #pragma unroll
            for (int p = 0; p < 2; p++) {
                // parallel b_j (independent of the serial chain)
                float b1 = fmaf(c1[p][0], k[p][0], -c2[p][0] * inD[p]);
                float b2 = fmaf(c1[p][0], k[p][1], -c2[p][0] * k[p][0]);
                float b3 = fmaf(c1[p][1], k[p][2], -c2[p][1] * k[p][1]);
                float b4 = fmaf(c1[p][1], k[p][3], -c2[p][1] * k[p][2]);
                float b5 = fmaf(c1[p][2], k[p][4], -c2[p][2] * k[p][3]);
                float b6 = fmaf(c1[p][2], k[p][5], -c2[p][2] * k[p][4]);
                float b7 = fmaf(c1[p][3], k[p][6], -c2[p][3] * k[p][5]);
                float b8 = fmaf(c1[p][3], k[p][7], -c2[p][3] * k[p][6]);
                // serial chain: 8 single FFMAs
                k[p][0] = fmaf(c1[p][0], inL[p], b1);
                k[p][1] = fmaf(c1[p][0], k[p][0], b2);
                k[p][2] = fmaf(c1[p][1], k[p][1], b3);
                k[p][3] = fmaf(c1[p][1], k[p][2], b4);
                k[p][4] = fmaf(c1[p][2], k[p][3], b5);
                k[p][5] = fmaf(c1[p][2], k[p][4], b6);
                k[p][6] = fmaf(c1[p][3], k[p][5], b7);
                k[p][7] = fmaf(c1[p][3], k[p][6], b8);
            }
        }
        #pragma unroll
        for (int p = 0; p < 2; p++) {
            inD[p] = inL[p];
            // shuffle for the NEXT step, issued as soon as k8 is ready
            inL[p] = __shfl_up_sync(0xffffffffu, k[p][7], 1, 8);
            if (t == 0) inL[p] = 1.0f;                     // left boundary
        }
    }

    // thread t=7 owns cols 57..64 -> k[p][5] = K[62][62]
    float v = (t == 7) ? (wgt[0] * k[0][5] + wgt[1] * k[1][5]) : 0.0f;
    // deterministic warp butterfly sum (fixed shuffle sequence)
    #pragma unroll
    for (int off = 16; off > 0; off >>= 1)
        v += __shfl_xor_sync(0xffffffffu, v, off);
    if (lane == 0) sh_res[warp] = v;
    __syncthreads();

    // ======== publish block partial + last-block fixed-order reduction ========
    if (threadIdx.x == 0) {
        g_block[blockIdx.x] = (sh_res[0] + sh_res[1]) + (sh_res[2] + sh_res[3]);
        __threadfence();
        unsigned tt = atomicAdd(&g_done, 1u);
        sh_last = (tt == NBLOCKS - 1);
    }
    __syncthreads();

    if (sh_last) {
        float s = 0.0f;
        #pragma unroll 1
        for (int i = threadIdx.x; i < NBLOCKS; i += THREADS_PER_BLOCK)
            s += g_block[i];
        sh_red[threadIdx.x] = s;
        __syncthreads();
        #pragma unroll
        for (int off = THREADS_PER_BLOCK / 2; off > 0; off >>= 1) {
            if (threadIdx.x < off) sh_red[threadIdx.x] += sh_red[threadIdx.x + off];
            __syncthreads();
        }
        if (threadIdx.x == 0) {
            out[0] = sh_red[0] * (1.0f / 4096.0f);
            g_done = 0;   // reset for next graph replay
        }
    }
}

extern "C" void kernel_launch(void* const* d_in, const int* in_sizes, int n_in,
                              void* d_out, int out_size)
{
    // Expected order: x [64*32*5], y [64*32*5], sigma_param [4].
    const float* x = nullptr;
    const float* yy = nullptr;
    const float* sp = nullptr;
    for (int i = 0; i < n_in; i++) {
        if (in_sizes[i] == CH - 1) { sp = (const float*)d_in[i]; }
        else if (!x)               { x  = (const float*)d_in[i]; }
        else if (!yy)              { yy = (const float*)d_in[i]; }
    }

    sig_kernel<<<NBLOCKS, THREADS_PER_BLOCK>>>(x, yy, sp, (float*)d_out);
}